// round 14
// baseline (speedup 1.0000x reference)
#include <cuda_runtime.h>
#include <cstdint>

// out[n, d, b] = unique_weights[indices[n], d] * input_values[n, d, b]
// N=16384, U=1024, D=128, B=16, fp32.  256 MiB compulsory HBM traffic.
//
// R12 (8 KiB tiles, depth-2, 8 CTAs/SM): 36.8us, DRAM 72.6%, occ 92.8%.
// This round: depth-3 ring at 8 KiB (24 KiB/CTA, still 8 CTAs/SM = 192 KiB/SM)
// -> 2 bulk loads in flight per CTA at ZERO occupancy cost.

#define N_POS 16384
#define U_DIM 1024
#define D_DIM 128
#define B_DIM 16

#define TILE_BYTES  8192                  // 8 KiB per bulk copy
#define TILE_F4     (TILE_BYTES / 16)     // 512 float4 per tile
#define THREADS     256                   // 2 float4 per thread per tile
#define DEPTH       3
#define N_TILES     (N_POS * D_DIM * B_DIM * 4 / TILE_BYTES)  // 16384

__device__ __forceinline__ uint32_t smem_u32(const void* p) {
    uint32_t a;
    asm("{ .reg .u64 t; cvta.to.shared.u64 t, %1; cvt.u32.u64 %0, t; }"
        : "=r"(a) : "l"(p));
    return a;
}

__device__ __forceinline__ void mbar_init(uint32_t mbar, uint32_t count) {
    asm volatile("mbarrier.init.shared.b64 [%0], %1;" :: "r"(mbar), "r"(count) : "memory");
}

__device__ __forceinline__ void mbar_expect_tx(uint32_t mbar, uint32_t bytes) {
    asm volatile("mbarrier.arrive.expect_tx.shared.b64 _, [%0], %1;"
                 :: "r"(mbar), "r"(bytes) : "memory");
}

__device__ __forceinline__ void bulk_g2s(uint32_t dst_smem, const void* src_gmem,
                                         uint32_t bytes, uint32_t mbar) {
    asm volatile("cp.async.bulk.shared::cluster.global.mbarrier::complete_tx::bytes "
                 "[%0], [%1], %2, [%3];"
                 :: "r"(dst_smem), "l"(src_gmem), "r"(bytes), "r"(mbar) : "memory");
}

__device__ __forceinline__ void mbar_wait(uint32_t mbar, uint32_t parity) {
    asm volatile(
        "{\n\t"
        ".reg .pred P;\n\t"
        "WAIT_%=:\n\t"
        "mbarrier.try_wait.parity.acquire.cta.shared::cta.b64 P, [%0], %1, 0x989680;\n\t"
        "@P bra.uni DONE_%=;\n\t"
        "bra.uni WAIT_%=;\n\t"
        "DONE_%=:\n\t"
        "}"
        :: "r"(mbar), "r"(parity) : "memory");
}

__global__ void __launch_bounds__(THREADS) diag_scale_tma8k3_kernel(
    const float* __restrict__ x,          // [N, D, B]
    const float* __restrict__ w,          // [U, D]
    const int* __restrict__ idx,          // [N] (int32)
    float* __restrict__ out)              // [N, D, B]
{
    __shared__ alignas(128) float4 buf[DEPTH][TILE_F4];   // 3 x 8 KiB
    __shared__ alignas(8) unsigned long long mbar_s[DEPTH];

    const int tid = threadIdx.x;
    uint32_t mba[DEPTH], bufa[DEPTH];
    #pragma unroll
    for (int i = 0; i < DEPTH; i++) {
        mba[i]  = smem_u32(&mbar_s[i]);
        bufa[i] = smem_u32(&buf[i][0]);
    }

    if (tid == 0) {
        #pragma unroll
        for (int i = 0; i < DEPTH; i++) mbar_init(mba[i], 1);
    }
    __syncthreads();

    const int G = gridDim.x;
    const int t0 = blockIdx.x;

    // Prologue: prefetch first DEPTH tiles.
    if (tid == 0) {
        #pragma unroll
        for (int i = 0; i < DEPTH; i++) {
            const int t = t0 + i * G;
            if (t < N_TILES) {
                mbar_expect_tx(mba[i], TILE_BYTES);
                bulk_g2s(bufa[i], (const char*)x + (size_t)t * TILE_BYTES,
                         TILE_BYTES, mba[i]);
            }
        }
    }

    int ph[DEPTH] = {0, 0, 0};
    int k = 0;
    for (int t = t0; t < N_TILES; t += G, k++) {
        const int s = k % DEPTH;

        // Wait for this tile's data.
        mbar_wait(mba[s], ph[s]);
        ph[s] ^= 1;

        const float4* __restrict__ bp = buf[s];
        float4* __restrict__ op = reinterpret_cast<float4*>(out) + (size_t)t * TILE_F4;
        const unsigned int gbase = (unsigned int)t * TILE_F4;

        // 2 float4 per thread; consecutive lanes -> consecutive 16B
        // (conflict-free LDS.128, fully coalesced STG.128).
        float4 v[2];
        float  wv[2];
        #pragma unroll
        for (int j = 0; j < 2; j++) {
            const int f4i = tid + j * THREADS;
            v[j] = bp[f4i];
            const unsigned int row = (gbase + (unsigned int)f4i) >> 2;  // 4 f4 per row
            const unsigned int n = row >> 7;
            const unsigned int d = row & 127;
            const unsigned int u = (unsigned int)__ldg(&idx[n]) & (U_DIM - 1);
            wv[j] = __ldg(&w[(size_t)u * D_DIM + d]);
        }
        #pragma unroll
        for (int j = 0; j < 2; j++) {
            const int f4i = tid + j * THREADS;
            float4 r = v[j];
            r.x *= wv[j]; r.y *= wv[j]; r.z *= wv[j]; r.w *= wv[j];
            op[f4i] = r;
        }

        __syncthreads();   // everyone done reading buf[s]; safe to refill

        const int tn = t + DEPTH * G;
        if (tn < N_TILES && tid == 0) {
            mbar_expect_tx(mba[s], TILE_BYTES);
            bulk_g2s(bufa[s], (const char*)x + (size_t)tn * TILE_BYTES,
                     TILE_BYTES, mba[s]);
        }
    }
}

extern "C" void kernel_launch(void* const* d_in, const int* in_sizes, int n_in,
                              void* d_out, int out_size)
{
    // Bind by element count — robust to metadata ordering.
    const float* x = nullptr;    // N*D*B = 33,554,432
    const float* w = nullptr;    // U*D   = 131,072
    const int* idx = nullptr;    // N     = 16,384
    for (int i = 0; i < n_in; i++) {
        if (in_sizes[i] == N_POS * D_DIM * B_DIM)   x   = (const float*)d_in[i];
        else if (in_sizes[i] == U_DIM * D_DIM)      w   = (const float*)d_in[i];
        else if (in_sizes[i] == N_POS)              idx = (const int*)d_in[i];
    }
    float* out = (float*)d_out;

    // 8 CTAs/SM x 148 SMs = 1184 resident CTAs; 16384 tiles, grid-stride.
    const int blocks = 1184;
    diag_scale_tma8k3_kernel<<<blocks, THREADS>>>(x, w, idx, out);
}

// round 15
// speedup vs baseline: 1.0720x; 1.0720x over previous
#include <cuda_runtime.h>
#include <cstdint>

// out[n, d, b] = unique_weights[indices[n], d] * input_values[n, d, b]
// N=16384, U=1024, D=128, B=16, fp32.  256 MiB compulsory HBM traffic.
//
// R12 structure (best: 36.8us kernel, DRAM 72.6%, occ 92.8%): 8 KiB tiles,
// depth-2 ring, 8 CTAs/SM, bulk TMA reads + plain STG.128 writes.
// New: one 8 KiB tile == exactly one n (128 rows x 4 f4). Producer loads
// idx[t] once and bulk-copies the 512 B weight row w[u] on the SAME mbarrier
// (expect_tx = 8192+512). Consumers read weights via LDS broadcast — kills
// the 1024 redundant idx/w LDGs per tile and their address math.

#define N_POS 16384
#define U_DIM 1024
#define D_DIM 128
#define B_DIM 16

#define TILE_BYTES  8192                  // 8 KiB per bulk copy (== one n)
#define W_BYTES     512                   // one weight row, 128 floats
#define TOT_BYTES   (TILE_BYTES + W_BYTES)
#define TILE_F4     (TILE_BYTES / 16)     // 512 float4 per tile
#define THREADS     256                   // 2 float4 per thread per tile
#define N_TILES     (N_POS * D_DIM * B_DIM * 4 / TILE_BYTES)  // 16384 (== N)

__device__ __forceinline__ uint32_t smem_u32(const void* p) {
    uint32_t a;
    asm("{ .reg .u64 t; cvta.to.shared.u64 t, %1; cvt.u32.u64 %0, t; }"
        : "=r"(a) : "l"(p));
    return a;
}

__device__ __forceinline__ void mbar_init(uint32_t mbar, uint32_t count) {
    asm volatile("mbarrier.init.shared.b64 [%0], %1;" :: "r"(mbar), "r"(count) : "memory");
}

__device__ __forceinline__ void mbar_expect_tx(uint32_t mbar, uint32_t bytes) {
    asm volatile("mbarrier.arrive.expect_tx.shared.b64 _, [%0], %1;"
                 :: "r"(mbar), "r"(bytes) : "memory");
}

__device__ __forceinline__ void bulk_g2s(uint32_t dst_smem, const void* src_gmem,
                                         uint32_t bytes, uint32_t mbar) {
    asm volatile("cp.async.bulk.shared::cluster.global.mbarrier::complete_tx::bytes "
                 "[%0], [%1], %2, [%3];"
                 :: "r"(dst_smem), "l"(src_gmem), "r"(bytes), "r"(mbar) : "memory");
}

__device__ __forceinline__ void mbar_wait(uint32_t mbar, uint32_t parity) {
    asm volatile(
        "{\n\t"
        ".reg .pred P;\n\t"
        "WAIT_%=:\n\t"
        "mbarrier.try_wait.parity.acquire.cta.shared::cta.b64 P, [%0], %1, 0x989680;\n\t"
        "@P bra.uni DONE_%=;\n\t"
        "bra.uni WAIT_%=;\n\t"
        "DONE_%=:\n\t"
        "}"
        :: "r"(mbar), "r"(parity) : "memory");
}

__global__ void __launch_bounds__(THREADS) diag_scale_tma_wrow_kernel(
    const float* __restrict__ x,          // [N, D, B]
    const float* __restrict__ w,          // [U, D]
    const int* __restrict__ idx,          // [N] (int32)
    float* __restrict__ out)              // [N, D, B]
{
    __shared__ alignas(128) float4 buf[2][TILE_F4];     // 2 x 8 KiB (x data)
    __shared__ alignas(128) float  wrow[2][D_DIM];      // 2 x 512 B (weight row)
    __shared__ alignas(8) unsigned long long mbar_s[2];

    const int tid = threadIdx.x;
    const uint32_t mba[2]  = { smem_u32(&mbar_s[0]),  smem_u32(&mbar_s[1]) };
    const uint32_t bufa[2] = { smem_u32(&buf[0][0]),  smem_u32(&buf[1][0]) };
    const uint32_t wra[2]  = { smem_u32(&wrow[0][0]), smem_u32(&wrow[1][0]) };

    if (tid == 0) {
        mbar_init(mba[0], 1);
        mbar_init(mba[1], 1);
    }
    __syncthreads();

    const int G = gridDim.x;
    const int t0 = blockIdx.x;

    // Prologue: prefetch first two tiles (+ their weight rows).
    if (tid == 0) {
        #pragma unroll
        for (int i = 0; i < 2; i++) {
            const int t = t0 + i * G;
            if (t < N_TILES) {
                const unsigned int u = (unsigned int)__ldg(&idx[t]) & (U_DIM - 1);
                mbar_expect_tx(mba[i], TOT_BYTES);
                bulk_g2s(bufa[i], (const char*)x + (size_t)t * TILE_BYTES,
                         TILE_BYTES, mba[i]);
                bulk_g2s(wra[i], (const char*)(w + (size_t)u * D_DIM),
                         W_BYTES, mba[i]);
            }
        }
    }

    int ph[2] = {0, 0};
    int k = 0;
    for (int t = t0; t < N_TILES; t += G, k++) {
        const int s = k & 1;

        // Wait for this tile's x data AND weight row.
        mbar_wait(mba[s], ph[s]);
        ph[s] ^= 1;

        const float4* __restrict__ bp = buf[s];
        const float*  __restrict__ wp = wrow[s];
        float4* __restrict__ op = reinterpret_cast<float4*>(out) + (size_t)t * TILE_F4;

        // 2 float4 per thread; consecutive lanes -> consecutive 16B
        // (conflict-free LDS.128, broadcast 4B weight LDS, coalesced STG.128).
        float4 v[2];
        float  wv[2];
        #pragma unroll
        for (int j = 0; j < 2; j++) {
            const int f4i = tid + j * THREADS;
            v[j]  = bp[f4i];
            wv[j] = wp[f4i >> 2];          // d = f4i/4 (4 f4 per d-row)
        }
        #pragma unroll
        for (int j = 0; j < 2; j++) {
            const int f4i = tid + j * THREADS;
            float4 r = v[j];
            r.x *= wv[j]; r.y *= wv[j]; r.z *= wv[j]; r.w *= wv[j];
            op[f4i] = r;
        }

        __syncthreads();   // everyone done reading buf[s]/wrow[s]; safe to refill

        const int tn = t + 2 * G;
        if (tn < N_TILES && tid == 0) {
            const unsigned int u = (unsigned int)__ldg(&idx[tn]) & (U_DIM - 1);
            mbar_expect_tx(mba[s], TOT_BYTES);
            bulk_g2s(bufa[s], (const char*)x + (size_t)tn * TILE_BYTES,
                     TILE_BYTES, mba[s]);
            bulk_g2s(wra[s], (const char*)(w + (size_t)u * D_DIM),
                     W_BYTES, mba[s]);
        }
    }
}

extern "C" void kernel_launch(void* const* d_in, const int* in_sizes, int n_in,
                              void* d_out, int out_size)
{
    // Bind by element count — robust to metadata ordering.
    const float* x = nullptr;    // N*D*B = 33,554,432
    const float* w = nullptr;    // U*D   = 131,072
    const int* idx = nullptr;    // N     = 16,384
    for (int i = 0; i < n_in; i++) {
        if (in_sizes[i] == N_POS * D_DIM * B_DIM)   x   = (const float*)d_in[i];
        else if (in_sizes[i] == U_DIM * D_DIM)      w   = (const float*)d_in[i];
        else if (in_sizes[i] == N_POS)              idx = (const int*)d_in[i];
    }
    float* out = (float*)d_out;

    // 8 CTAs/SM x 148 SMs = 1184 resident CTAs; 16384 tiles, grid-stride.
    const int blocks = 1184;
    diag_scale_tma_wrow_kernel<<<blocks, THREADS>>>(x, w, idx, out);
}

// round 17
// speedup vs baseline: 1.1146x; 1.0398x over previous
#include <cuda_runtime.h>
#include <cstdint>

// out[n, d, b] = unique_weights[indices[n], d] * input_values[n, d, b]
// N=16384, U=1024, D=128, B=16, fp32.  256 MiB compulsory HBM traffic.
//
// R12 family (best: 36.8us, DRAM 72.6%, occ 92.8%): bulk TMA G2S reads +
// plain STG.128 writes, depth-2 ring, 8 CTAs/SM (thread-capped).
// Single change vs R12: 4 KiB tiles (8 KiB smem/CTA = 64 KiB/SM), freeing
// ~64 KiB more L1 carveout for the store stream / gathers, and reducing
// consumer work to exactly 1 LDS.128 + 1 STG.128 per thread per tile.

#define N_POS 16384
#define U_DIM 1024
#define D_DIM 128
#define B_DIM 16

#define TILE_BYTES  4096                  // 4 KiB per bulk copy
#define TILE_F4     (TILE_BYTES / 16)     // 256 float4 per tile
#define THREADS     256                   // 1 float4 per thread per tile
#define N_TILES     (N_POS * D_DIM * B_DIM * 4 / TILE_BYTES)  // 32768

__device__ __forceinline__ uint32_t smem_u32(const void* p) {
    uint32_t a;
    asm("{ .reg .u64 t; cvta.to.shared.u64 t, %1; cvt.u32.u64 %0, t; }"
        : "=r"(a) : "l"(p));
    return a;
}

__device__ __forceinline__ void mbar_init(uint32_t mbar, uint32_t count) {
    asm volatile("mbarrier.init.shared.b64 [%0], %1;" :: "r"(mbar), "r"(count) : "memory");
}

__device__ __forceinline__ void mbar_expect_tx(uint32_t mbar, uint32_t bytes) {
    asm volatile("mbarrier.arrive.expect_tx.shared.b64 _, [%0], %1;"
                 :: "r"(mbar), "r"(bytes) : "memory");
}

__device__ __forceinline__ void bulk_g2s(uint32_t dst_smem, const void* src_gmem,
                                         uint32_t bytes, uint32_t mbar) {
    asm volatile("cp.async.bulk.shared::cluster.global.mbarrier::complete_tx::bytes "
                 "[%0], [%1], %2, [%3];"
                 :: "r"(dst_smem), "l"(src_gmem), "r"(bytes), "r"(mbar) : "memory");
}

__device__ __forceinline__ void mbar_wait(uint32_t mbar, uint32_t parity) {
    asm volatile(
        "{\n\t"
        ".reg .pred P;\n\t"
        "WAIT_%=:\n\t"
        "mbarrier.try_wait.parity.acquire.cta.shared::cta.b64 P, [%0], %1, 0x989680;\n\t"
        "@P bra.uni DONE_%=;\n\t"
        "bra.uni WAIT_%=;\n\t"
        "DONE_%=:\n\t"
        "}"
        :: "r"(mbar), "r"(parity) : "memory");
}

__global__ void __launch_bounds__(THREADS) diag_scale_tma4k_kernel(
    const float* __restrict__ x,          // [N, D, B]
    const float* __restrict__ w,          // [U, D]
    const int* __restrict__ idx,          // [N] (int32)
    float* __restrict__ out)              // [N, D, B]
{
    __shared__ alignas(128) float4 buf[2][TILE_F4];   // 2 x 4 KiB
    __shared__ alignas(8) unsigned long long mbar_s[2];

    const int tid = threadIdx.x;
    const uint32_t mba[2] = { smem_u32(&mbar_s[0]), smem_u32(&mbar_s[1]) };
    const uint32_t bufa[2] = { smem_u32(&buf[0][0]), smem_u32(&buf[1][0]) };

    if (tid == 0) {
        mbar_init(mba[0], 1);
        mbar_init(mba[1], 1);
    }
    __syncthreads();

    const int G = gridDim.x;
    const int t0 = blockIdx.x;

    // Prologue: prefetch first two tiles.
    if (tid == 0) {
        if (t0 < N_TILES) {
            mbar_expect_tx(mba[0], TILE_BYTES);
            bulk_g2s(bufa[0], (const char*)x + (size_t)t0 * TILE_BYTES, TILE_BYTES, mba[0]);
        }
        if (t0 + G < N_TILES) {
            mbar_expect_tx(mba[1], TILE_BYTES);
            bulk_g2s(bufa[1], (const char*)x + (size_t)(t0 + G) * TILE_BYTES, TILE_BYTES, mba[1]);
        }
    }

    int ph[2] = {0, 0};
    int k = 0;
    for (int t = t0; t < N_TILES; t += G, k++) {
        const int s = k & 1;

        // Wait for this tile's data.
        mbar_wait(mba[s], ph[s]);
        ph[s] ^= 1;

        const float4* __restrict__ bp = buf[s];
        float4* __restrict__ op = reinterpret_cast<float4*>(out) + (size_t)t * TILE_F4;
        const unsigned int gbase = (unsigned int)t * TILE_F4;

        // Exactly 1 float4 per thread: LDS.128 + broadcast gathers + STG.128.
        const int f4i = tid;
        float4 v = bp[f4i];
        const unsigned int row = (gbase + (unsigned int)f4i) >> 2;  // 4 f4 per row
        const unsigned int n = row >> 7;
        const unsigned int d = row & 127;
        const unsigned int u = (unsigned int)__ldg(&idx[n]) & (U_DIM - 1);
        const float wv = __ldg(&w[(size_t)u * D_DIM + d]);

        v.x *= wv; v.y *= wv; v.z *= wv; v.w *= wv;
        op[f4i] = v;

        __syncthreads();   // everyone done reading buf[s]; safe to refill

        const int tn = t + 2 * G;
        if (tn < N_TILES && tid == 0) {
            mbar_expect_tx(mba[s], TILE_BYTES);
            bulk_g2s(bufa[s], (const char*)x + (size_t)tn * TILE_BYTES,
                     TILE_BYTES, mba[s]);
        }
    }
}

extern "C" void kernel_launch(void* const* d_in, const int* in_sizes, int n_in,
                              void* d_out, int out_size)
{
    // Bind by element count — robust to metadata ordering.
    const float* x = nullptr;    // N*D*B = 33,554,432
    const float* w = nullptr;    // U*D   = 131,072
    const int* idx = nullptr;    // N     = 16,384
    for (int i = 0; i < n_in; i++) {
        if (in_sizes[i] == N_POS * D_DIM * B_DIM)   x   = (const float*)d_in[i];
        else if (in_sizes[i] == U_DIM * D_DIM)      w   = (const float*)d_in[i];
        else if (in_sizes[i] == N_POS)              idx = (const int*)d_in[i];
    }
    float* out = (float*)d_out;

    // 8 CTAs/SM x 148 SMs = 1184 resident CTAs; 32768 tiles, grid-stride.
    const int blocks = 1184;
    diag_scale_tma4k_kernel<<<blocks, THREADS>>>(x, w, idx, out);
}